// round 10
// baseline (speedup 1.0000x reference)
#include <cuda_runtime.h>
#include <cstdint>
#include <cstddef>

// Problem constants
#define B_SZ 8
#define L_SZ 2048
#define D_SZ 1024
#define H_SZ 120
#define HP   128              // H padded to 128 (pad cols are exactly 0)
#define NTOT (B_SZ * L_SZ)    // 16384

// ---------------- device scratch (static: no allocation allowed) ------------
__device__ float g_Wf[D_SZ * HP];                 // fused weight, [d][h] layout
__device__ float g_bf[HP];                        // fused bias
__device__ float g_UT[(size_t)B_SZ * HP * L_SZ];  // u transposed per batch [b][h][n]
__device__ float g_norm[NTOT];                    // ||u_n||^2

// ---------------- f32x2 packed-FMA helpers (sm_103a FFMA2 path) -------------
__device__ __forceinline__ unsigned long long pack2(float x, float y) {
    unsigned long long r;
    asm("mov.b64 %0, {%1, %2};" : "=l"(r) : "f"(x), "f"(y));
    return r;
}
__device__ __forceinline__ void unpack2(unsigned long long v, float& x, float& y) {
    asm("mov.b64 {%0, %1}, %2;" : "=f"(x), "=f"(y) : "l"(v));
}
__device__ __forceinline__ void fma2(unsigned long long& d,
                                     unsigned long long a, unsigned long long b) {
    asm("fma.rn.f32x2 %0, %1, %2, %0;" : "+l"(d) : "l"(a), "l"(b));
}

// ============================================================================
// Kernel A: fold q_weight and the Mahalanobis factor into one weight:
//   Wf[d][h] = sum_h' q_weight[h'][d] * W[h'][h]     (h < 120, else 0)
//   bf[h]    = sum_h' q_bias[h'] * W[h'][h]
// Tiny (31 MF). grid = 1025 blocks x 128 threads; block 1024 does the bias.
// ============================================================================
__global__ void k_fuseW(const float* __restrict__ qw,
                        const float* __restrict__ qb,
                        const float* __restrict__ W) {
    int h = threadIdx.x;       // 0..127
    int d = blockIdx.x;
    if (d < D_SZ) {
        float acc = 0.f;
        if (h < H_SZ) {
            #pragma unroll 4
            for (int hp = 0; hp < H_SZ; hp++)
                acc = fmaf(W[hp * H_SZ + h], qw[hp * D_SZ + d], acc);
        }
        g_Wf[d * HP + h] = acc;
    } else {
        float acc = 0.f;
        if (h < H_SZ) {
            #pragma unroll 4
            for (int hp = 0; hp < H_SZ; hp++)
                acc = fmaf(W[hp * H_SZ + h], qb[hp], acc);
        }
        g_bf[h] = acc;
    }
}

// ============================================================================
// Kernel B: projection GEMM  U[n][h] = query[n][:] @ Wf[:][h] + bf[h]
// M=16384, N=128, K=1024. BM=64, BN=128, BK=16, 256 threads,
// thread tile 4 rows x 8 cols (4 f32x2 pairs over j). Emits U^T and ||u||^2.
// ============================================================================
__global__ void __launch_bounds__(256)
k_proj(const float* __restrict__ q) {
    __shared__ float Qs[16][65];     // [k][i], padded vs bank conflicts
    __shared__ float Ws[16][128];    // [k][h]
    __shared__ float red[64][17];

    const int t  = threadIdx.x;
    const int tx = t & 15;           // col group
    const int ty = t >> 4;           // row group (0..15)
    const int m0 = blockIdx.x * 64;

    unsigned long long acc[4][4];
    #pragma unroll
    for (int r = 0; r < 4; r++)
        #pragma unroll
        for (int p = 0; p < 4; p++) acc[r][p] = 0ull;

    for (int k0 = 0; k0 < D_SZ; k0 += 16) {
        // load query tile 64x16 (one float4 per thread)
        {
            int i  = t >> 2;
            int kq = (t & 3) * 4;
            float4 v = *(const float4*)&q[(size_t)(m0 + i) * D_SZ + k0 + kq];
            Qs[kq + 0][i] = v.x; Qs[kq + 1][i] = v.y;
            Qs[kq + 2][i] = v.z; Qs[kq + 3][i] = v.w;
        }
        // load Wf tile 16x128 (two float4 per thread)
        {
            int kk = t >> 4;
            int j8 = (t & 15) * 8;
            const float* src = &g_Wf[(size_t)(k0 + kk) * HP + j8];
            *(float4*)&Ws[kk][j8]     = *(const float4*)src;
            *(float4*)&Ws[kk][j8 + 4] = *(const float4*)(src + 4);
        }
        __syncthreads();
        #pragma unroll
        for (int k = 0; k < 16; k++) {
            unsigned long long ad[4];
            #pragma unroll
            for (int r = 0; r < 4; r++) {
                float a = Qs[k][ty * 4 + r];
                ad[r] = pack2(a, a);
            }
            #pragma unroll
            for (int p = 0; p < 4; p++) {
                unsigned long long bb =
                    *(const unsigned long long*)&Ws[k][p * 32 + tx * 2];
                #pragma unroll
                for (int r = 0; r < 4; r++) fma2(acc[r][p], ad[r], bb);
            }
        }
        __syncthreads();
    }

    // epilogue: add bias, write U^T (scattered) and row-norm partials
    const int b   = m0 >> 11;        // / 2048
    const int nb0 = m0 & 2047;
    const size_t utb = (size_t)b * HP * L_SZ;
    float psum[4] = {0.f, 0.f, 0.f, 0.f};
    #pragma unroll
    for (int r = 0; r < 4; r++) {
        const int nn = nb0 + ty * 4 + r;
        #pragma unroll
        for (int p = 0; p < 4; p++) {
            int j = p * 32 + tx * 2;
            float ux, uy;
            unpack2(acc[r][p], ux, uy);
            ux += g_bf[j];
            uy += g_bf[j + 1];
            g_UT[utb + (size_t)j * L_SZ + nn]       = ux;
            g_UT[utb + (size_t)(j + 1) * L_SZ + nn] = uy;
            psum[r] = fmaf(ux, ux, psum[r]);
            psum[r] = fmaf(uy, uy, psum[r]);
        }
    }
    #pragma unroll
    for (int r = 0; r < 4; r++) red[ty * 4 + r][tx] = psum[r];
    __syncthreads();
    if (t < 64) {
        float s = 0.f;
        #pragma unroll
        for (int x = 0; x < 16; x++) s += red[t][x];
        g_norm[m0 + t] = s;
    }
}

// ============================================================================
// Kernel C: pairwise RBF + double-exp + row sums + IN-KERNEL normalize.
// BM=64 rows per CTA (owns full rows -> CTA-local softmax denominators),
// BN=64 j-tile, K=128 in 2 chunks of 64. 128 threads = 8 ty x 16 tx.
// Thread tile: 8 rows (4 f32x2 ROW-pairs, natural LDS.64 from UiT) x 4 cols.
// Per k: 16 FFMA2 vs 4 LDS.64 + 4 LDS + 4 movs -> fma-pipe bound by design.
// Pass 1 streams unnormalized exp(exp(..)) to gmem + accumulates row sums;
// pass 2 (same CTA, post-__syncthreads) rescales its own 512KB slice (L2-hot).
// ============================================================================
__global__ void __launch_bounds__(128)
k_scores(float* __restrict__ out, const float* __restrict__ pinv) {
    __shared__ float UiT[HP][64];    // [k][i] transposed, 32 KB (reused: inv row sums)
    __shared__ float Ujc[64][64];    // K-chunk x j, 16 KB (reused: reduction scratch)

    const int t  = threadIdx.x;
    const int tx = t & 15;           // 0..15 (j groups)
    const int ty = t >> 4;           // 0..7  (row groups of 8)
    const int m0 = blockIdx.x * 64;
    const int b  = m0 >> 11;
    const int nb0 = m0 & 2047;
    const size_t utb = (size_t)b * HP * L_SZ;
    const float sc   = pinv[0] * pinv[0];
    const float cneg = -0.5f * sc;

    // fill UiT (once): 128k x 64i from g_UT, coalesced float4 both sides
    #pragma unroll
    for (int c = 0; c < 16; c++) {
        int idx = c * 128 + t;           // float4 index 0..2047
        int k   = idx >> 4;
        int i4  = (idx & 15) * 4;
        *(float4*)&UiT[k][i4] =
            *(const float4*)&g_UT[utb + (size_t)k * L_SZ + nb0 + i4];
    }
    float ni[8];
    #pragma unroll
    for (int r = 0; r < 8; r++) ni[r] = g_norm[m0 + ty * 8 + r];
    float sacc[8];
    #pragma unroll
    for (int r = 0; r < 8; r++) sacc[r] = 0.f;

    for (int j0 = 0; j0 < L_SZ; j0 += 64) {
        unsigned long long acc[4][4];
        #pragma unroll
        for (int rp = 0; rp < 4; rp++)
            #pragma unroll
            for (int jc = 0; jc < 4; jc++) acc[rp][jc] = 0ull;

        for (int kc = 0; kc < HP; kc += 64) {
            __syncthreads();             // prev consumers done with Ujc (also covers UiT fill)
            // load Uj K-chunk (64k x 64j) — coalesced
            #pragma unroll
            for (int c = 0; c < 8; c++) {
                int idx = c * 128 + t;   // float4 index 0..1023
                int k   = idx >> 4;
                int j4  = (idx & 15) * 4;
                *(float4*)&Ujc[k][j4] =
                    *(const float4*)&g_UT[utb + (size_t)(kc + k) * L_SZ + j0 + j4];
            }
            __syncthreads();

            #pragma unroll 8
            for (int k = 0; k < 64; k++) {
                unsigned long long a[4];
                #pragma unroll
                for (int rp = 0; rp < 4; rp++)
                    a[rp] = *(const unsigned long long*)&UiT[kc + k][ty * 8 + rp * 2];
                #pragma unroll
                for (int jc = 0; jc < 4; jc++) {
                    float bv = Ujc[k][tx + 16 * jc];
                    unsigned long long bd = pack2(bv, bv);
                    #pragma unroll
                    for (int rp = 0; rp < 4; rp++) fma2(acc[rp][jc], a[rp], bd);
                }
            }
        }

        // epilogue: RBF + exp, accumulate row sums, store unnormalized
        #pragma unroll
        for (int jc = 0; jc < 4; jc++) {
            int j = j0 + tx + 16 * jc;
            float nj = __ldg(&g_norm[b * L_SZ + j]);
            #pragma unroll
            for (int rp = 0; rp < 4; rp++) {
                float d0, d1;
                unpack2(acc[rp][jc], d0, d1);
                float s0 = __expf(cneg * fmaf(-2.f, d0, ni[rp * 2]     + nj));
                float s1 = __expf(cneg * fmaf(-2.f, d1, ni[rp * 2 + 1] + nj));
                float e0 = __expf(s0);
                float e1 = __expf(s1);
                sacc[rp * 2]     += e0;
                sacc[rp * 2 + 1] += e1;
                out[(size_t)(m0 + ty * 8 + rp * 2)     * L_SZ + j] = e0;
                out[(size_t)(m0 + ty * 8 + rp * 2 + 1) * L_SZ + j] = e1;
            }
        }
    }

    // ---- deterministic row-sum reduction (Ujc as scratch: 64 x 17 floats) ----
    __syncthreads();
    float* red = &Ujc[0][0];
    #pragma unroll
    for (int r = 0; r < 8; r++) red[(ty * 8 + r) * 17 + tx] = sacc[r];
    __syncthreads();
    float* invs = &UiT[0][0];            // UiT no longer needed
    if (t < 64) {
        float s = 0.f;
        #pragma unroll
        for (int x = 0; x < 16; x++) s += red[t * 17 + x];
        invs[t] = 1.0f / s;
    }
    __syncthreads();                      // invs visible + pass-1 gmem writes visible

    // ---- in-kernel normalize of this CTA's 64x2048 slice (mostly L2-hot) ----
    {
        float4* base = (float4*)(out + (size_t)m0 * L_SZ);
        const int n4 = 64 * (L_SZ / 4);  // 32768 float4s
        for (int idx = t; idx < n4; idx += 128) {
            const int row = idx >> 9;    // idx*4 / 2048
            const float inv = invs[row];
            float4 v = base[idx];
            v.x *= inv; v.y *= inv; v.z *= inv; v.w *= inv;
            base[idx] = v;
        }
    }
}

// ============================================================================
extern "C" void kernel_launch(void* const* d_in, const int* in_sizes, int n_in,
                              void* d_out, int out_size) {
    const float* query = (const float*)d_in[0];
    // d_in[1] = key : unused by the reference computation
    const float* qw    = (const float*)d_in[2];
    const float* qb    = (const float*)d_in[3];
    const float* W     = (const float*)d_in[4];
    const float* pinv  = (const float*)d_in[5];
    float* out = (float*)d_out;

    k_fuseW<<<D_SZ + 1, 128>>>(qw, qb, W);
    k_proj<<<NTOT / 64, 256>>>(query);
    k_scores<<<NTOT / 64, 128>>>(out, pinv);
}

// round 12
// speedup vs baseline: 1.5977x; 1.5977x over previous
#include <cuda_runtime.h>
#include <cuda_bf16.h>
#include <cstdint>
#include <cstddef>

// Problem constants
#define B_SZ 8
#define L_SZ 2048
#define D_SZ 1024
#define H_SZ 120
#define HP   128              // H padded to 128 (pad cols are exactly 0)
#define NTOT (B_SZ * L_SZ)    // 16384

// ---------------- device scratch (static: no allocation allowed) ------------
__device__ float g_Wf[D_SZ * HP];                   // fused weight, [d][h]
__device__ float g_bf[HP];                          // fused bias
__device__ __nv_bfloat16 g_Uhi[(size_t)NTOT * HP];  // u hi-part, [n][h]
__device__ __nv_bfloat16 g_Ulo[(size_t)NTOT * HP];  // u lo-part, [n][h]
__device__ float g_norm[NTOT];                      // ||u_n||^2 (fp32 exact)

// ---------------- f32x2 packed-FMA helpers (k_proj) -------------------------
__device__ __forceinline__ unsigned long long pack2(float x, float y) {
    unsigned long long r;
    asm("mov.b64 %0, {%1, %2};" : "=l"(r) : "f"(x), "f"(y));
    return r;
}
__device__ __forceinline__ void unpack2(unsigned long long v, float& x, float& y) {
    asm("mov.b64 {%0, %1}, %2;" : "=f"(x), "=f"(y) : "l"(v));
}
__device__ __forceinline__ void fma2(unsigned long long& d,
                                     unsigned long long a, unsigned long long b) {
    asm("fma.rn.f32x2 %0, %1, %2, %0;" : "+l"(d) : "l"(a), "l"(b));
}

// ---------------- base-ISA tensor helpers (sm_80+, no 'a' features) ---------
__device__ __forceinline__ uint32_t smem_u32(const void* p) {
    uint32_t a;
    asm("{ .reg .u64 t; cvta.to.shared.u64 t, %1; cvt.u32.u64 %0, t; }"
        : "=r"(a) : "l"(p));
    return a;
}
__device__ __forceinline__ void ldsm_x4(uint32_t& r0, uint32_t& r1,
                                        uint32_t& r2, uint32_t& r3, uint32_t addr) {
    asm volatile("ldmatrix.sync.aligned.m8n8.x4.shared.b16 {%0,%1,%2,%3}, [%4];"
                 : "=r"(r0), "=r"(r1), "=r"(r2), "=r"(r3) : "r"(addr));
}
__device__ __forceinline__ void mma_bf16(float* c, const uint32_t* a,
                                         uint32_t b0, uint32_t b1) {
    asm volatile("mma.sync.aligned.m16n8k16.row.col.f32.bf16.bf16.f32 "
                 "{%0,%1,%2,%3}, {%4,%5,%6,%7}, {%8,%9}, {%0,%1,%2,%3};"
                 : "+f"(c[0]), "+f"(c[1]), "+f"(c[2]), "+f"(c[3])
                 : "r"(a[0]), "r"(a[1]), "r"(a[2]), "r"(a[3]), "r"(b0), "r"(b1));
}

// ============================================================================
// Kernel A: Wf = qw^T @ W fold (+ bias fold). 4 independent accumulators
// break the serial FMA chain (was latency-bound at 21us).
// ============================================================================
__global__ void k_fuseW(const float* __restrict__ qw,
                        const float* __restrict__ qb,
                        const float* __restrict__ W) {
    int h = threadIdx.x;
    int d = blockIdx.x;
    float a0 = 0.f, a1 = 0.f, a2 = 0.f, a3 = 0.f;
    if (d < D_SZ) {
        if (h < H_SZ) {
            #pragma unroll
            for (int hp = 0; hp < H_SZ; hp += 4) {
                a0 = fmaf(W[(hp + 0) * H_SZ + h], qw[(hp + 0) * D_SZ + d], a0);
                a1 = fmaf(W[(hp + 1) * H_SZ + h], qw[(hp + 1) * D_SZ + d], a1);
                a2 = fmaf(W[(hp + 2) * H_SZ + h], qw[(hp + 2) * D_SZ + d], a2);
                a3 = fmaf(W[(hp + 3) * H_SZ + h], qw[(hp + 3) * D_SZ + d], a3);
            }
        }
        g_Wf[d * HP + h] = (a0 + a1) + (a2 + a3);
    } else {
        if (h < H_SZ) {
            #pragma unroll
            for (int hp = 0; hp < H_SZ; hp += 4) {
                a0 = fmaf(W[(hp + 0) * H_SZ + h], qb[hp + 0], a0);
                a1 = fmaf(W[(hp + 1) * H_SZ + h], qb[hp + 1], a1);
                a2 = fmaf(W[(hp + 2) * H_SZ + h], qb[hp + 2], a2);
                a3 = fmaf(W[(hp + 3) * H_SZ + h], qb[hp + 3], a3);
            }
        }
        g_bf[h] = (a0 + a1) + (a2 + a3);
    }
}

// ============================================================================
// Kernel B: projection GEMM U = query @ Wf + bf (FFMA2 path).
// Epilogue emits bf16 hi/lo split [n][h] + fp32 ||u||^2.
// ============================================================================
__global__ void __launch_bounds__(256)
k_proj(const float* __restrict__ q) {
    __shared__ float Qs[16][65];
    __shared__ float Ws[16][128];
    __shared__ float red[64][17];

    const int t  = threadIdx.x;
    const int tx = t & 15;
    const int ty = t >> 4;
    const int m0 = blockIdx.x * 64;

    unsigned long long acc[4][4];
    #pragma unroll
    for (int r = 0; r < 4; r++)
        #pragma unroll
        for (int p = 0; p < 4; p++) acc[r][p] = 0ull;

    for (int k0 = 0; k0 < D_SZ; k0 += 16) {
        {
            int i  = t >> 2;
            int kq = (t & 3) * 4;
            float4 v = *(const float4*)&q[(size_t)(m0 + i) * D_SZ + k0 + kq];
            Qs[kq + 0][i] = v.x; Qs[kq + 1][i] = v.y;
            Qs[kq + 2][i] = v.z; Qs[kq + 3][i] = v.w;
        }
        {
            int kk = t >> 4;
            int j8 = (t & 15) * 8;
            const float* src = &g_Wf[(size_t)(k0 + kk) * HP + j8];
            *(float4*)&Ws[kk][j8]     = *(const float4*)src;
            *(float4*)&Ws[kk][j8 + 4] = *(const float4*)(src + 4);
        }
        __syncthreads();
        #pragma unroll
        for (int k = 0; k < 16; k++) {
            unsigned long long ad[4];
            #pragma unroll
            for (int r = 0; r < 4; r++) {
                float a = Qs[k][ty * 4 + r];
                ad[r] = pack2(a, a);
            }
            #pragma unroll
            for (int p = 0; p < 4; p++) {
                unsigned long long bb =
                    *(const unsigned long long*)&Ws[k][p * 32 + tx * 2];
                #pragma unroll
                for (int r = 0; r < 4; r++) fma2(acc[r][p], ad[r], bb);
            }
        }
        __syncthreads();
    }

    float psum[4] = {0.f, 0.f, 0.f, 0.f};
    #pragma unroll
    for (int r = 0; r < 4; r++) {
        const int n = m0 + ty * 4 + r;
        #pragma unroll
        for (int p = 0; p < 4; p++) {
            int j = p * 32 + tx * 2;
            float ux, uy;
            unpack2(acc[r][p], ux, uy);
            ux += g_bf[j];
            uy += g_bf[j + 1];
            __nv_bfloat16 hx = __float2bfloat16(ux);
            __nv_bfloat16 hy = __float2bfloat16(uy);
            __nv_bfloat16 lx = __float2bfloat16(ux - __bfloat162float(hx));
            __nv_bfloat16 ly = __float2bfloat16(uy - __bfloat162float(hy));
            __nv_bfloat162 hv; hv.x = hx; hv.y = hy;
            __nv_bfloat162 lv; lv.x = lx; lv.y = ly;
            *(__nv_bfloat162*)&g_Uhi[(size_t)n * HP + j] = hv;
            *(__nv_bfloat162*)&g_Ulo[(size_t)n * HP + j] = lv;
            psum[r] = fmaf(ux, ux, psum[r]);
            psum[r] = fmaf(uy, uy, psum[r]);
        }
    }
    #pragma unroll
    for (int r = 0; r < 4; r++) red[ty * 4 + r][tx] = psum[r];
    __syncthreads();
    if (t < 64) {
        float s = 0.f;
        #pragma unroll
        for (int x = 0; x < 16; x++) s += red[t][x];
        g_norm[m0 + t] = s;
    }
}

// ============================================================================
// Kernel C: mma.sync bf16 pairwise kernel (base-ISA tensor path).
// CTA = 128 rows, 256 threads (8 warps x m16 strip), sweeps 16 j-tiles of 128.
// 3-product hi/lo split: D = Ahi.Bhi + Alo.Bhi + Ahi.Blo  (fp32 accum).
// A fragments register-resident across the whole j sweep (staged via B bufs).
// Smem tile layout: row-major 256B/row, 16B-chunk XOR swizzle c^=(row&7)
// -> conflict-free ldmatrix. Epilogue: RBF double-exp from register C frags,
// register-local row sums (quad shfl butterfly, deterministic), then CTA-local
// normalize of its 128x2048 slice.
// ============================================================================
#define SMB_NJ   0                       // 128 f32: ||u_j||^2 of current tile
#define SMB_INV  512                     // 128 f32: inverse row sums
#define SMB_B0   1024                    // 32 KB tile buffer (hi)
#define SMB_B1   (SMB_B0 + 32768)        // 32 KB tile buffer (lo)
#define SM_TOTAL_MMA (SMB_B1 + 32768)    // 66560 bytes

// stage a 128x128 bf16 tile (row-major [row][HP]) into swizzled smem
__device__ __forceinline__ void load_tile(char* dst, const __nv_bfloat16* src, int t) {
    #pragma unroll
    for (int it = 0; it < 8; it++) {
        int idx = it * 256 + t;          // 16B-chunk index, 2048 total
        int row = idx >> 4;
        int c   = idx & 15;
        uint32_t off = (uint32_t)row * 256u + 16u * (uint32_t)(c ^ (row & 7));
        *(uint4*)(dst + off) = *(const uint4*)(src + (size_t)row * HP + c * 8);
    }
}

__global__ void __launch_bounds__(256)
k_scores_mma(float* __restrict__ out, const float* __restrict__ pinv) {
    extern __shared__ char smem[];
    float* njs  = (float*)(smem + SMB_NJ);
    float* invs = (float*)(smem + SMB_INV);
    char*  bufH = smem + SMB_B0;
    char*  bufL = smem + SMB_B1;

    const int t    = threadIdx.x;
    const int w    = t >> 5;             // warp 0..7 -> m-strip rows [w*16, w*16+16)
    const int lane = t & 31;
    const int g    = lane >> 2;          // group 0..7
    const int tid  = lane & 3;
    const int m0   = blockIdx.x * 128;   // 16 CTAs per batch, no straddle
    const int b    = m0 >> 11;
    const int jb   = b * L_SZ;
    const float sc   = pinv[0] * pinv[0];
    const float cneg = -0.5f * sc;

    // ---- stage A (this CTA's rows) through B buffers, capture fragments ----
    load_tile(bufH, g_Uhi + (size_t)m0 * HP, t);
    load_tile(bufL, g_Ulo + (size_t)m0 * HP, t);
    __syncthreads();

    uint32_t ahi[8][4], alo[8][4];
    {
        // A ldmatrix.x4 tiles: t0=(rows 0-7,kc), t1=(rows 8-15,kc),
        //                      t2=(rows 0-7,kc+1), t3=(rows 8-15,kc+1)
        const int rowL  = w * 16 + ((lane >> 3) & 1) * 8 + (lane & 7);
        const int cbitA = (lane >> 4) & 1;
        const int r7    = rowL & 7;
        const uint32_t baseH = smem_u32(bufH) + (uint32_t)rowL * 256u;
        const uint32_t baseL = smem_u32(bufL) + (uint32_t)rowL * 256u;
        #pragma unroll
        for (int ks = 0; ks < 8; ks++) {
            uint32_t kx = 16u * (uint32_t)((2 * ks + cbitA) ^ r7);
            ldsm_x4(ahi[ks][0], ahi[ks][1], ahi[ks][2], ahi[ks][3], baseH + kx);
            ldsm_x4(alo[ks][0], alo[ks][1], alo[ks][2], alo[ks][3], baseL + kx);
        }
    }

    const float ni0 = g_norm[m0 + w * 16 + g];
    const float ni1 = g_norm[m0 + w * 16 + g + 8];
    float rs0 = 0.f, rs1 = 0.f;

    // B ldmatrix.x4 tiles: t0=(nf,kc), t1=(nf,kc+1), t2=(nf+1,kc), t3=(nf+1,kc+1)
    const int jlo   = ((lane >> 4) & 1) * 8 + (lane & 7);
    const int cbitB = (lane >> 3) & 1;
    const int j7    = jlo & 7;
    const uint32_t bHb = smem_u32(bufH) + (uint32_t)jlo * 256u;
    const uint32_t bLb = smem_u32(bufL) + (uint32_t)jlo * 256u;

    for (int tile = 0; tile < 16; tile++) {
        const int j0 = tile * 128;
        __syncthreads();                 // prior tile's ldmatrix/epilogue done
        load_tile(bufH, g_Uhi + (size_t)(jb + j0) * HP, t);
        load_tile(bufL, g_Ulo + (size_t)(jb + j0) * HP, t);
        if (t < 32)
            *(float4*)&njs[t * 4] = *(const float4*)&g_norm[jb + j0 + t * 4];
        __syncthreads();

        float C[16][4];
        #pragma unroll
        for (int nf = 0; nf < 16; nf++)
            #pragma unroll
            for (int x = 0; x < 4; x++) C[nf][x] = 0.f;

        #pragma unroll
        for (int ks = 0; ks < 8; ks++) {
            uint32_t kx = 16u * (uint32_t)((2 * ks + cbitB) ^ j7);
            #pragma unroll
            for (int nfp = 0; nfp < 8; nfp++) {     // Bhi pass: Ahi.Bhi + Alo.Bhi
                uint32_t b0, b1, b2, b3;
                ldsm_x4(b0, b1, b2, b3, bHb + (uint32_t)nfp * 4096u + kx);
                mma_bf16(C[2 * nfp],     ahi[ks], b0, b1);
                mma_bf16(C[2 * nfp],     alo[ks], b0, b1);
                mma_bf16(C[2 * nfp + 1], ahi[ks], b2, b3);
                mma_bf16(C[2 * nfp + 1], alo[ks], b2, b3);
            }
            #pragma unroll
            for (int nfp = 0; nfp < 8; nfp++) {     // Blo pass: Ahi.Blo
                uint32_t b0, b1, b2, b3;
                ldsm_x4(b0, b1, b2, b3, bLb + (uint32_t)nfp * 4096u + kx);
                mma_bf16(C[2 * nfp],     ahi[ks], b0, b1);
                mma_bf16(C[2 * nfp + 1], ahi[ks], b2, b3);
            }
        }

        // epilogue: C[nf] = {D[g][tid*2], D[g][tid*2+1], D[g+8][tid*2], D[g+8][tid*2+1]}
        float* orow0 = out + (size_t)(m0 + w * 16 + g)     * L_SZ + j0;
        float* orow1 = out + (size_t)(m0 + w * 16 + g + 8) * L_SZ + j0;
        #pragma unroll
        for (int nf = 0; nf < 16; nf++) {
            const int jc = nf * 8 + tid * 2;
            const float nj0 = njs[jc], nj1 = njs[jc + 1];
            float e00 = __expf(__expf(cneg * fmaf(-2.f, C[nf][0], ni0 + nj0)));
            float e01 = __expf(__expf(cneg * fmaf(-2.f, C[nf][1], ni0 + nj1)));
            float e10 = __expf(__expf(cneg * fmaf(-2.f, C[nf][2], ni1 + nj0)));
            float e11 = __expf(__expf(cneg * fmaf(-2.f, C[nf][3], ni1 + nj1)));
            rs0 += e00 + e01;
            rs1 += e10 + e11;
            float2 o0; o0.x = e00; o0.y = e01;
            float2 o1; o1.x = e10; o1.y = e11;
            *(float2*)(orow0 + jc) = o0;
            *(float2*)(orow1 + jc) = o1;
        }
    }

    // quad butterfly row-sum reduction (commutative adds -> deterministic)
    rs0 += __shfl_xor_sync(0xFFFFFFFFu, rs0, 1);
    rs0 += __shfl_xor_sync(0xFFFFFFFFu, rs0, 2);
    rs1 += __shfl_xor_sync(0xFFFFFFFFu, rs1, 1);
    rs1 += __shfl_xor_sync(0xFFFFFFFFu, rs1, 2);
    if (tid == 0) {
        invs[w * 16 + g]     = 1.0f / rs0;
        invs[w * 16 + g + 8] = 1.0f / rs1;
    }
    __syncthreads();

    // in-kernel normalize of this CTA's 128x2048 slice (L2-hot)
    {
        float4* base = (float4*)(out + (size_t)m0 * L_SZ);
        const int n4 = 128 * (L_SZ / 4); // 65536 float4s
        for (int idx = t; idx < n4; idx += 256) {
            const float inv = invs[idx >> 9];
            float4 v = base[idx];
            v.x *= inv; v.y *= inv; v.z *= inv; v.w *= inv;
            base[idx] = v;
        }
    }
}

// ============================================================================
extern "C" void kernel_launch(void* const* d_in, const int* in_sizes, int n_in,
                              void* d_out, int out_size) {
    const float* query = (const float*)d_in[0];
    // d_in[1] = key : unused by the reference computation
    const float* qw    = (const float*)d_in[2];
    const float* qb    = (const float*)d_in[3];
    const float* W     = (const float*)d_in[4];
    const float* pinv  = (const float*)d_in[5];
    float* out = (float*)d_out;

    cudaFuncSetAttribute(k_scores_mma,
                         cudaFuncAttributeMaxDynamicSharedMemorySize, SM_TOTAL_MMA);

    k_fuseW<<<D_SZ + 1, 128>>>(qw, qb, W);
    k_proj<<<NTOT / 64, 256>>>(query);
    k_scores_mma<<<NTOT / 128, 256, SM_TOTAL_MMA>>>(out, pinv);
}

// round 13
// speedup vs baseline: 1.9835x; 1.2415x over previous
#include <cuda_runtime.h>
#include <cuda_bf16.h>
#include <cstdint>
#include <cstddef>

// Problem constants
#define B_SZ 8
#define L_SZ 2048
#define D_SZ 1024
#define H_SZ 120
#define HP   128              // H padded to 128 (pad cols are exactly 0)
#define NTOT (B_SZ * L_SZ)    // 16384

// ---------------- device scratch (static: no allocation allowed) ------------
__device__ __nv_bfloat16 g_WfT_hi[(size_t)HP * D_SZ];  // fused weight^T hi [h][d]
__device__ __nv_bfloat16 g_WfT_lo[(size_t)HP * D_SZ];  // fused weight^T lo [h][d]
__device__ float g_bf[HP];                             // fused bias
__device__ __nv_bfloat16 g_Uhi[(size_t)NTOT * HP];     // u hi-part, [n][h]
__device__ __nv_bfloat16 g_Ulo[(size_t)NTOT * HP];     // u lo-part, [n][h]
__device__ float g_norm[NTOT];                         // ||u_n||^2

// ---------------- base-ISA tensor helpers (sm_80+, no 'a' features) ---------
__device__ __forceinline__ uint32_t smem_u32(const void* p) {
    uint32_t a;
    asm("{ .reg .u64 t; cvta.to.shared.u64 t, %1; cvt.u32.u64 %0, t; }"
        : "=r"(a) : "l"(p));
    return a;
}
__device__ __forceinline__ void ldsm_x4(uint32_t& r0, uint32_t& r1,
                                        uint32_t& r2, uint32_t& r3, uint32_t addr) {
    asm volatile("ldmatrix.sync.aligned.m8n8.x4.shared.b16 {%0,%1,%2,%3}, [%4];"
                 : "=r"(r0), "=r"(r1), "=r"(r2), "=r"(r3) : "r"(addr));
}
__device__ __forceinline__ void mma_bf16(float* c, const uint32_t* a,
                                         uint32_t b0, uint32_t b1) {
    asm volatile("mma.sync.aligned.m16n8k16.row.col.f32.bf16.bf16.f32 "
                 "{%0,%1,%2,%3}, {%4,%5,%6,%7}, {%8,%9}, {%0,%1,%2,%3};"
                 : "+f"(c[0]), "+f"(c[1]), "+f"(c[2]), "+f"(c[3])
                 : "r"(a[0]), "r"(a[1]), "r"(a[2]), "r"(a[3]), "r"(b0), "r"(b1));
}

// stage a 128x128 bf16 tile (row-major, given stride) into swizzled smem
// smem layout: 256B/row, 16B-chunk XOR swizzle c ^= (row & 7)  [bench-validated]
__device__ __forceinline__ void load_tile(char* dst, const __nv_bfloat16* src,
                                          int t, int stride) {
    #pragma unroll
    for (int it = 0; it < 8; it++) {
        int idx = it * 256 + t;          // 16B-chunk index, 2048 total
        int row = idx >> 4;
        int c   = idx & 15;
        uint32_t off = (uint32_t)row * 256u + 16u * (uint32_t)(c ^ (row & 7));
        *(uint4*)(dst + off) = *(const uint4*)(src + (size_t)row * stride + c * 8);
    }
}

// stage a 128x128 fp32 tile, splitting to hi/lo bf16 swizzled tiles on the fly
__device__ __forceinline__ void load_tile_split(char* dH, char* dL,
                                                const float* src, int t, int stride) {
    #pragma unroll
    for (int it = 0; it < 8; it++) {
        int idx = it * 256 + t;          // 16B-bf16-chunk index (8 floats)
        int row = idx >> 4;
        int c   = idx & 15;
        const float* s = src + (size_t)row * stride + c * 8;
        float4 v0 = *(const float4*)s;
        float4 v1 = *(const float4*)(s + 4);
        float xs[8] = {v0.x, v0.y, v0.z, v0.w, v1.x, v1.y, v1.z, v1.w};
        __nv_bfloat162 hv[4], lv[4];
        #pragma unroll
        for (int i = 0; i < 4; i++) {
            __nv_bfloat16 hx = __float2bfloat16(xs[2 * i]);
            __nv_bfloat16 hy = __float2bfloat16(xs[2 * i + 1]);
            hv[i].x = hx; hv[i].y = hy;
            lv[i].x = __float2bfloat16(xs[2 * i]     - __bfloat162float(hx));
            lv[i].y = __float2bfloat16(xs[2 * i + 1] - __bfloat162float(hy));
        }
        uint32_t off = (uint32_t)row * 256u + 16u * (uint32_t)(c ^ (row & 7));
        *(uint4*)(dH + off) = *(uint4*)hv;
        *(uint4*)(dL + off) = *(uint4*)lv;
    }
}

// ============================================================================
// Kernel A: fold q_weight & Mahalanobis factor; emit WfT hi/lo bf16 + bias.
// 8 independent accumulators (was latency-bound at 13us with 4).
// ============================================================================
__global__ void k_fuseW(const float* __restrict__ qw,
                        const float* __restrict__ qb,
                        const float* __restrict__ W) {
    int h = threadIdx.x;
    int d = blockIdx.x;
    float a[8] = {0.f, 0.f, 0.f, 0.f, 0.f, 0.f, 0.f, 0.f};
    if (d < D_SZ) {
        if (h < H_SZ) {
            #pragma unroll
            for (int hp = 0; hp < H_SZ; hp += 8)
                #pragma unroll
                for (int i = 0; i < 8; i++)
                    a[i] = fmaf(W[(hp + i) * H_SZ + h], qw[(hp + i) * D_SZ + d], a[i]);
        }
        float wf = ((a[0] + a[1]) + (a[2] + a[3])) + ((a[4] + a[5]) + (a[6] + a[7]));
        __nv_bfloat16 hi = __float2bfloat16(wf);
        g_WfT_hi[(size_t)h * D_SZ + d] = hi;
        g_WfT_lo[(size_t)h * D_SZ + d] = __float2bfloat16(wf - __bfloat162float(hi));
    } else {
        if (h < H_SZ) {
            #pragma unroll
            for (int hp = 0; hp < H_SZ; hp += 8)
                #pragma unroll
                for (int i = 0; i < 8; i++)
                    a[i] = fmaf(W[(hp + i) * H_SZ + h], qb[hp + i], a[i]);
        }
        g_bf[h] = ((a[0] + a[1]) + (a[2] + a[3])) + ((a[4] + a[5]) + (a[6] + a[7]));
    }
}

// ============================================================================
// Kernel B: projection GEMM U = query @ Wf + bf on mma.sync tensor path.
// CTA = 128 rows, 256 threads (8 warps x m16), N=128, K=1024 in 8 chunks.
// A = query chunk (fp32 -> hi/lo split during staging), B = WfT hi/lo.
// 3-product split accum in fp32 C frags (persist across chunks).
// Epilogue: +bias, write g_Uhi/g_Ulo, quad-shfl row norms (deterministic).
// ============================================================================
#define SMP_AHI 0
#define SMP_ALO 32768
#define SMP_BHI 65536
#define SMP_BLO 98304
#define SM_TOTAL_PROJ 131072

__global__ void __launch_bounds__(256)
k_proj_mma(const float* __restrict__ q) {
    extern __shared__ char smem[];
    char* bufAH = smem + SMP_AHI;
    char* bufAL = smem + SMP_ALO;
    char* bufBH = smem + SMP_BHI;
    char* bufBL = smem + SMP_BLO;

    const int t    = threadIdx.x;
    const int w    = t >> 5;
    const int lane = t & 31;
    const int g    = lane >> 2;
    const int tid  = lane & 3;
    const int m0   = blockIdx.x * 128;

    float C[16][4];
    #pragma unroll
    for (int nf = 0; nf < 16; nf++)
        #pragma unroll
        for (int x = 0; x < 4; x++) C[nf][x] = 0.f;

    // A-fragment addressing (bench-validated mapping)
    const int rowL  = w * 16 + ((lane >> 3) & 1) * 8 + (lane & 7);
    const int cbitA = (lane >> 4) & 1;
    const int r7    = rowL & 7;
    const uint32_t aHb = smem_u32(bufAH) + (uint32_t)rowL * 256u;
    const uint32_t aLb = smem_u32(bufAL) + (uint32_t)rowL * 256u;
    // B-fragment addressing (bench-validated mapping)
    const int jlo   = ((lane >> 4) & 1) * 8 + (lane & 7);
    const int cbitB = (lane >> 3) & 1;
    const int j7    = jlo & 7;
    const uint32_t bHb = smem_u32(bufBH) + (uint32_t)jlo * 256u;
    const uint32_t bLb = smem_u32(bufBL) + (uint32_t)jlo * 256u;

    for (int kc = 0; kc < 8; kc++) {
        __syncthreads();                 // previous chunk's ldsm complete
        load_tile_split(bufAH, bufAL, q + (size_t)m0 * D_SZ + kc * 128, t, D_SZ);
        load_tile(bufBH, g_WfT_hi + kc * 128, t, D_SZ);
        load_tile(bufBL, g_WfT_lo + kc * 128, t, D_SZ);
        __syncthreads();

        #pragma unroll
        for (int ks = 0; ks < 8; ks++) {
            uint32_t kxA = 16u * (uint32_t)((2 * ks + cbitA) ^ r7);
            uint32_t ahi[4], alo[4];
            ldsm_x4(ahi[0], ahi[1], ahi[2], ahi[3], aHb + kxA);
            ldsm_x4(alo[0], alo[1], alo[2], alo[3], aLb + kxA);
            uint32_t kxB = 16u * (uint32_t)((2 * ks + cbitB) ^ j7);
            #pragma unroll
            for (int nfp = 0; nfp < 8; nfp++) {     // Bhi: Ahi.Bhi + Alo.Bhi
                uint32_t b0, b1, b2, b3;
                ldsm_x4(b0, b1, b2, b3, bHb + (uint32_t)nfp * 4096u + kxB);
                mma_bf16(C[2 * nfp],     ahi, b0, b1);
                mma_bf16(C[2 * nfp],     alo, b0, b1);
                mma_bf16(C[2 * nfp + 1], ahi, b2, b3);
                mma_bf16(C[2 * nfp + 1], alo, b2, b3);
            }
            #pragma unroll
            for (int nfp = 0; nfp < 8; nfp++) {     // Blo: Ahi.Blo
                uint32_t b0, b1, b2, b3;
                ldsm_x4(b0, b1, b2, b3, bLb + (uint32_t)nfp * 4096u + kxB);
                mma_bf16(C[2 * nfp],     ahi, b0, b1);
                mma_bf16(C[2 * nfp + 1], ahi, b2, b3);
            }
        }
    }

    // epilogue: u = C + bias; hi/lo split write; row norms via quad butterfly
    const int row0 = m0 + w * 16 + g;
    const int row1 = row0 + 8;
    float rs0 = 0.f, rs1 = 0.f;
    #pragma unroll
    for (int nf = 0; nf < 16; nf++) {
        const int jc = nf * 8 + tid * 2;
        const float b0 = g_bf[jc], b1 = g_bf[jc + 1];
        float u00 = C[nf][0] + b0, u01 = C[nf][1] + b1;
        float u10 = C[nf][2] + b0, u11 = C[nf][3] + b1;
        __nv_bfloat162 h0, l0, h1, l1;
        h0.x = __float2bfloat16(u00); h0.y = __float2bfloat16(u01);
        l0.x = __float2bfloat16(u00 - __bfloat162float(h0.x));
        l0.y = __float2bfloat16(u01 - __bfloat162float(h0.y));
        h1.x = __float2bfloat16(u10); h1.y = __float2bfloat16(u11);
        l1.x = __float2bfloat16(u10 - __bfloat162float(h1.x));
        l1.y = __float2bfloat16(u11 - __bfloat162float(h1.y));
        *(__nv_bfloat162*)&g_Uhi[(size_t)row0 * HP + jc] = h0;
        *(__nv_bfloat162*)&g_Ulo[(size_t)row0 * HP + jc] = l0;
        *(__nv_bfloat162*)&g_Uhi[(size_t)row1 * HP + jc] = h1;
        *(__nv_bfloat162*)&g_Ulo[(size_t)row1 * HP + jc] = l1;
        rs0 += u00 * u00 + u01 * u01;
        rs1 += u10 * u10 + u11 * u11;
    }
    rs0 += __shfl_xor_sync(0xFFFFFFFFu, rs0, 1);
    rs0 += __shfl_xor_sync(0xFFFFFFFFu, rs0, 2);
    rs1 += __shfl_xor_sync(0xFFFFFFFFu, rs1, 1);
    rs1 += __shfl_xor_sync(0xFFFFFFFFu, rs1, 2);
    if (tid == 0) {
        g_norm[row0] = rs0;
        g_norm[row1] = rs1;
    }
}

// ============================================================================
// Kernel C: mma.sync bf16 pairwise kernel (unchanged from R12 WIN).
// ============================================================================
#define SMB_NJ   0
#define SMB_INV  512
#define SMB_B0   1024
#define SMB_B1   (SMB_B0 + 32768)
#define SM_TOTAL_MMA (SMB_B1 + 32768)

__global__ void __launch_bounds__(256)
k_scores_mma(float* __restrict__ out, const float* __restrict__ pinv) {
    extern __shared__ char smem[];
    float* njs  = (float*)(smem + SMB_NJ);
    float* invs = (float*)(smem + SMB_INV);
    char*  bufH = smem + SMB_B0;
    char*  bufL = smem + SMB_B1;

    const int t    = threadIdx.x;
    const int w    = t >> 5;
    const int lane = t & 31;
    const int g    = lane >> 2;
    const int tid  = lane & 3;
    const int m0   = blockIdx.x * 128;
    const int b    = m0 >> 11;
    const int jb   = b * L_SZ;
    const float sc   = pinv[0] * pinv[0];
    const float cneg = -0.5f * sc;

    load_tile(bufH, g_Uhi + (size_t)m0 * HP, t, HP);
    load_tile(bufL, g_Ulo + (size_t)m0 * HP, t, HP);
    __syncthreads();

    uint32_t ahi[8][4], alo[8][4];
    {
        const int rowL  = w * 16 + ((lane >> 3) & 1) * 8 + (lane & 7);
        const int cbitA = (lane >> 4) & 1;
        const int r7    = rowL & 7;
        const uint32_t baseH = smem_u32(bufH) + (uint32_t)rowL * 256u;
        const uint32_t baseL = smem_u32(bufL) + (uint32_t)rowL * 256u;
        #pragma unroll
        for (int ks = 0; ks < 8; ks++) {
            uint32_t kx = 16u * (uint32_t)((2 * ks + cbitA) ^ r7);
            ldsm_x4(ahi[ks][0], ahi[ks][1], ahi[ks][2], ahi[ks][3], baseH + kx);
            ldsm_x4(alo[ks][0], alo[ks][1], alo[ks][2], alo[ks][3], baseL + kx);
        }
    }

    const float ni0 = g_norm[m0 + w * 16 + g];
    const float ni1 = g_norm[m0 + w * 16 + g + 8];
    float rs0 = 0.f, rs1 = 0.f;

    const int jlo   = ((lane >> 4) & 1) * 8 + (lane & 7);
    const int cbitB = (lane >> 3) & 1;
    const int j7    = jlo & 7;
    const uint32_t bHb = smem_u32(bufH) + (uint32_t)jlo * 256u;
    const uint32_t bLb = smem_u32(bufL) + (uint32_t)jlo * 256u;

    for (int tile = 0; tile < 16; tile++) {
        const int j0 = tile * 128;
        __syncthreads();
        load_tile(bufH, g_Uhi + (size_t)(jb + j0) * HP, t, HP);
        load_tile(bufL, g_Ulo + (size_t)(jb + j0) * HP, t, HP);
        if (t < 32)
            *(float4*)&njs[t * 4] = *(const float4*)&g_norm[jb + j0 + t * 4];
        __syncthreads();

        float C[16][4];
        #pragma unroll
        for (int nf = 0; nf < 16; nf++)
            #pragma unroll
            for (int x = 0; x < 4; x++) C[nf][x] = 0.f;

        #pragma unroll
        for (int ks = 0; ks < 8; ks++) {
            uint32_t kx = 16u * (uint32_t)((2 * ks + cbitB) ^ j7);
            #pragma unroll
            for (int nfp = 0; nfp < 8; nfp++) {
                uint32_t b0, b1, b2, b3;
                ldsm_x4(b0, b1, b2, b3, bHb + (uint32_t)nfp * 4096u + kx);
                mma_bf16(C[2 * nfp],     ahi[ks], b0, b1);
                mma_bf16(C[2 * nfp],     alo[ks], b0, b1);
                mma_bf16(C[2 * nfp + 1], ahi[ks], b2, b3);
                mma_bf16(C[2 * nfp + 1], alo[ks], b2, b3);
            }
            #pragma unroll
            for (int nfp = 0; nfp < 8; nfp++) {
                uint32_t b0, b1, b2, b3;
                ldsm_x4(b0, b1, b2, b3, bLb + (uint32_t)nfp * 4096u + kx);
                mma_bf16(C[2 * nfp],     ahi[ks], b0, b1);
                mma_bf16(C[2 * nfp + 1], ahi[ks], b2, b3);
            }
        }

        float* orow0 = out + (size_t)(m0 + w * 16 + g)     * L_SZ + j0;
        float* orow1 = out + (size_t)(m0 + w * 16 + g + 8) * L_SZ + j0;
        #pragma unroll
        for (int nf = 0; nf < 16; nf++) {
            const int jc = nf * 8 + tid * 2;
            const float nj0 = njs[jc], nj1 = njs[jc + 1];
            float e00 = __expf(__expf(cneg * fmaf(-2.f, C[nf][0], ni0 + nj0)));
            float e01 = __expf(__expf(cneg * fmaf(-2.f, C[nf][1], ni0 + nj1)));
            float e10 = __expf(__expf(cneg * fmaf(-2.f, C[nf][2], ni1 + nj0)));
            float e11 = __expf(__expf(cneg * fmaf(-2.f, C[nf][3], ni1 + nj1)));
            rs0 += e00 + e01;
            rs1 += e10 + e11;
            float2 o0; o0.x = e00; o0.y = e01;
            float2 o1; o1.x = e10; o1.y = e11;
            *(float2*)(orow0 + jc) = o0;
            *(float2*)(orow1 + jc) = o1;
        }
    }

    rs0 += __shfl_xor_sync(0xFFFFFFFFu, rs0, 1);
    rs0 += __shfl_xor_sync(0xFFFFFFFFu, rs0, 2);
    rs1 += __shfl_xor_sync(0xFFFFFFFFu, rs1, 1);
    rs1 += __shfl_xor_sync(0xFFFFFFFFu, rs1, 2);
    if (tid == 0) {
        invs[w * 16 + g]     = 1.0f / rs0;
        invs[w * 16 + g + 8] = 1.0f / rs1;
    }
    __syncthreads();

    {
        float4* base = (float4*)(out + (size_t)m0 * L_SZ);
        const int n4 = 128 * (L_SZ / 4);
        for (int idx = t; idx < n4; idx += 256) {
            const float inv = invs[idx >> 9];
            float4 v = base[idx];
            v.x *= inv; v.y *= inv; v.z *= inv; v.w *= inv;
            base[idx] = v;
        }
    }
}

// ============================================================================
extern "C" void kernel_launch(void* const* d_in, const int* in_sizes, int n_in,
                              void* d_out, int out_size) {
    const float* query = (const float*)d_in[0];
    // d_in[1] = key : unused by the reference computation
    const float* qw    = (const float*)d_in[2];
    const float* qb    = (const float*)d_in[3];
    const float* W     = (const float*)d_in[4];
    const float* pinv  = (const float*)d_in[5];
    float* out = (float*)d_out;

    cudaFuncSetAttribute(k_proj_mma,
                         cudaFuncAttributeMaxDynamicSharedMemorySize, SM_TOTAL_PROJ);
    cudaFuncSetAttribute(k_scores_mma,
                         cudaFuncAttributeMaxDynamicSharedMemorySize, SM_TOTAL_MMA);

    k_fuseW<<<D_SZ + 1, 128>>>(qw, qb, W);
    k_proj_mma<<<NTOT / 128, 256, SM_TOTAL_PROJ>>>(query);
    k_scores_mma<<<NTOT / 128, 256, SM_TOTAL_MMA>>>(out, pinv);
}